// round 4
// baseline (speedup 1.0000x reference)
#include <cuda_runtime.h>
#include <cuda_fp16.h>
#include <cstdint>
#include <math.h>

#define N_NODES 50000
#define E_EDGES 800000
#define H 128
#define MF 276
#define NTILES (E_EDGES / 128)      // 6250
#define NODE_TILES ((N_NODES + 127) / 128)  // 391
#define GRID_PERS 148

// ---------------------------------------------------------------------------
// Scratch (no cudaMalloc allowed)
// ---------------------------------------------------------------------------
__device__ float  g_hagg[N_NODES * H];
__device__ float  g_xagg[N_NODES * 3];
__device__ __half g_W1e[288 * 136];
__device__ __half g_W1c[288 * 136];
__device__ __half g_We2[128 * 136];
__device__ __half g_Wc2[128 * 136];
__device__ __half g_Wn1[256 * 136];
__device__ __half g_Wn2[128 * 136];

__device__ __forceinline__ uint32_t smem_u32(const void* p) {
    uint32_t a;
    asm("{ .reg .u64 t; cvta.to.shared.u64 t, %1; cvt.u32.u64 %0, t; }"
        : "=r"(a) : "l"(p));
    return a;
}
__device__ __forceinline__ float silu_f(float v) { return v / (1.f + __expf(-v)); }

__device__ __forceinline__ void red_add_v4(float* p, float a, float b, float c, float d) {
    asm volatile("red.global.add.v4.f32 [%0], {%1,%2,%3,%4};"
        :: "l"(p), "f"(a), "f"(b), "f"(c), "f"(d) : "memory");
}

// ---------------------------------------------------------------------------
// Warp-level fp16 GEMM: 8 warps in 4(M)x2(N), C tile 128x128, acc[2][8][4]
// ---------------------------------------------------------------------------
__device__ __forceinline__ void zero_acc(float (&acc)[2][8][4]) {
#pragma unroll
    for (int mt = 0; mt < 2; ++mt)
#pragma unroll
        for (int nt = 0; nt < 8; ++nt)
#pragma unroll
            for (int i = 0; i < 4; ++i) acc[mt][nt][i] = 0.f;
}

__device__ __forceinline__ void gemm_frag(uint32_t aBase, int aStride,
                                          uint32_t bBase, int ksteps,
                                          float (&acc)[2][8][4])
{
    const int lane = threadIdx.x & 31;
    const int wid  = threadIdx.x >> 5;
    const int wm   = wid & 3;
    const int wn   = wid >> 2;
    const int arow = wm * 32 + (lane & 15);
    const int acoff = (lane & 16) ? 8 : 0;
    const int brow = lane & 15;
    const int bcol = wn * 64 + ((lane & 16) ? 8 : 0);

    for (int ks = 0; ks < ksteps; ++ks) {
        const int k0 = ks * 16;
        uint32_t a[2][4];
#pragma unroll
        for (int mt = 0; mt < 2; ++mt) {
            uint32_t ad = aBase + (uint32_t)(((arow + mt * 16) * aStride + k0 + acoff) * 2);
            asm volatile("ldmatrix.sync.aligned.m8n8.x4.shared.b16 {%0,%1,%2,%3}, [%4];"
                : "=r"(a[mt][0]), "=r"(a[mt][1]), "=r"(a[mt][2]), "=r"(a[mt][3]) : "r"(ad));
        }
        uint32_t b[8][2];
#pragma unroll
        for (int nt2 = 0; nt2 < 4; ++nt2) {
            uint32_t bd = bBase + (uint32_t)(((k0 + brow) * 136 + bcol + nt2 * 16) * 2);
            asm volatile("ldmatrix.sync.aligned.m8n8.x4.trans.shared.b16 {%0,%1,%2,%3}, [%4];"
                : "=r"(b[2 * nt2][0]), "=r"(b[2 * nt2][1]),
                  "=r"(b[2 * nt2 + 1][0]), "=r"(b[2 * nt2 + 1][1]) : "r"(bd));
        }
#pragma unroll
        for (int mt = 0; mt < 2; ++mt)
#pragma unroll
            for (int nt = 0; nt < 8; ++nt)
                asm volatile("mma.sync.aligned.m16n8k16.row.col.f32.f16.f16.f32 "
                    "{%0,%1,%2,%3}, {%4,%5,%6,%7}, {%8,%9}, {%0,%1,%2,%3};"
                    : "+f"(acc[mt][nt][0]), "+f"(acc[mt][nt][1]),
                      "+f"(acc[mt][nt][2]), "+f"(acc[mt][nt][3])
                    : "r"(a[mt][0]), "r"(a[mt][1]), "r"(a[mt][2]), "r"(a[mt][3]),
                      "r"(b[nt][0]), "r"(b[nt][1]));
    }
}

__device__ __forceinline__ void epi_act(const float (&acc)[2][8][4],
                                        const float* __restrict__ sb, __half* act)
{
    const int lane = threadIdx.x & 31;
    const int wid  = threadIdx.x >> 5;
    const int wm = wid & 3, wn = wid >> 2;
#pragma unroll
    for (int mt = 0; mt < 2; ++mt)
#pragma unroll
        for (int nt = 0; nt < 8; ++nt) {
            const int row = wm * 32 + mt * 16 + (lane >> 2);
            const int col = wn * 64 + nt * 8 + (lane & 3) * 2;
            const float b0 = sb[col], b1 = sb[col + 1];
            *(half2*)(act + row * 136 + col) =
                __floats2half2_rn(silu_f(acc[mt][nt][0] + b0), silu_f(acc[mt][nt][1] + b1));
            *(half2*)(act + (row + 8) * 136 + col) =
                __floats2half2_rn(silu_f(acc[mt][nt][2] + b0), silu_f(acc[mt][nt][3] + b1));
        }
}

// ---------------------------------------------------------------------------
__global__ void prep_kernel(const float* __restrict__ We1, const float* __restrict__ Wc1,
                            const float* __restrict__ We2, const float* __restrict__ Wc2,
                            const float* __restrict__ Wn1, const float* __restrict__ Wn2)
{
    const int stride = gridDim.x * blockDim.x;
    const __half hz = __float2half_rn(0.f);
    for (int i = blockIdx.x * blockDim.x + threadIdx.x; i < 288 * 136; i += stride) {
        int k = i / 136, n = i % 136;
        bool ok = (k < MF) && (n < 128);
        g_W1e[i] = ok ? __float2half_rn(We1[k * 128 + n]) : hz;
        g_W1c[i] = ok ? __float2half_rn(Wc1[k * 128 + n]) : hz;
    }
    for (int i = blockIdx.x * blockDim.x + threadIdx.x; i < 256 * 136; i += stride) {
        int k = i / 136, n = i % 136;
        g_Wn1[i] = (n < 128) ? __float2half_rn(Wn1[k * 128 + n]) : hz;
    }
    for (int i = blockIdx.x * blockDim.x + threadIdx.x; i < 128 * 136; i += stride) {
        int k = i / 136, n = i % 136;
        bool ok = (n < 128);
        g_We2[i] = ok ? __float2half_rn(We2[k * 128 + n]) : hz;
        g_Wc2[i] = ok ? __float2half_rn(Wc2[k * 128 + n]) : hz;
        g_Wn2[i] = ok ? __float2half_rn(Wn2[k * 128 + n]) : hz;
    }
}

__global__ void zero_kernel()
{
    const int total = N_NODES * H + N_NODES * 3;
    for (int i = blockIdx.x * blockDim.x + threadIdx.x; i < total;
         i += gridDim.x * blockDim.x) {
        if (i < N_NODES * H) g_hagg[i] = 0.f;
        else                 g_xagg[i - N_NODES * H] = 0.f;
    }
}

// ---------------------------------------------------------------------------
// Persistent edge-chain kernel. MODE 0: edge MLP + att + h scatter.
//                               MODE 1: coord MLP + x scatter.
// smem: W1[288x136] | W2[128x136] | f[128x296] | act[128x136] | misc
// ---------------------------------------------------------------------------
#define EOF_W1   0
#define EOF_W2   78336
#define EOF_F    113152
#define EOF_ACT  188928
#define EOF_BIAS 223744
#define EOF_SATT 225280
#define EOF_DIFF 225792
#define EOF_DST  227840
#define EOF_SRC  228352
#define EDGE_SMEM 228864

template<int MODE>
__global__ void __launch_bounds__(256, 1)
edge_chain_kernel(const float* __restrict__ hmat, const float* __restrict__ coords,
                  const float* __restrict__ amat,
                  const int* __restrict__ src, const int* __restrict__ dst,
                  const __half* __restrict__ gW1, const __half* __restrict__ gW2,
                  const float* __restrict__ b1, const float* __restrict__ b2,
                  const float* __restrict__ headW, const float* __restrict__ headB)
{
    extern __shared__ __align__(16) char sm[];
    __half* sW1 = (__half*)(sm + EOF_W1);
    __half* sW2 = (__half*)(sm + EOF_W2);
    __half* fA  = (__half*)(sm + EOF_F);     // stride 296
    __half* act = (__half*)(sm + EOF_ACT);   // stride 136
    float* sb1  = (float*)(sm + EOF_BIAS);
    float* sb2  = sb1 + 128;
    float* shw  = sb2 + 128;
    float* satt = (float*)(sm + EOF_SATT);
    float* sdiff = (float*)(sm + EOF_DIFF);
    int* sdst = (int*)(sm + EOF_DST);
    int* ssrc = (int*)(sm + EOF_SRC);

    const uint32_t fU = smem_u32(fA), w1U = smem_u32(sW1);
    const uint32_t w2U = smem_u32(sW2), actU = smem_u32(act);
    const int tid = threadIdx.x;

    // resident weights + biases (once)
    for (int i = tid; i < 4896; i += 256) ((float4*)sW1)[i] = ((const float4*)gW1)[i];
    for (int i = tid; i < 2176; i += 256) ((float4*)sW2)[i] = ((const float4*)gW2)[i];
    if (tid < 128) { sb1[tid] = b1[tid]; sb2[tid] = b2[tid]; shw[tid] = headW[tid]; }
    const float hb0 = (MODE == 0) ? headB[0] : 0.f;
    __syncthreads();

    float acc[2][8][4];

    for (int t = blockIdx.x; t < NTILES; t += GRID_PERS) {
        const int e0 = t * 128;

        if (tid < 128) {
            const int e = e0 + tid;
            const int s_ = src[e], d_ = dst[e];
            ssrc[tid] = s_; sdst[tid] = d_;
            float dx = coords[s_ * 3 + 0] - coords[d_ * 3 + 0];
            float dy = coords[s_ * 3 + 1] - coords[d_ * 3 + 1];
            float dz = coords[s_ * 3 + 2] - coords[d_ * 3 + 2];
            float r  = sqrtf(dx * dx + dy * dy + dz * dz);
            if (MODE == 1) {
                sdiff[4 * tid + 0] = dx; sdiff[4 * tid + 1] = dy;
                sdiff[4 * tid + 2] = dz; sdiff[4 * tid + 3] = r;
            }
            __half* fr = fA + tid * 296;
            *(half2*)(fr + 256) = __floats2half2_rn(r, fabsf(dx));
            *(half2*)(fr + 258) = __floats2half2_rn(fabsf(dy), fabsf(dz));
            const half2 z2 = __floats2half2_rn(0.f, 0.f);
#pragma unroll
            for (int c = 276; c < 288; c += 2) *(half2*)(fr + c) = z2;
        }
        __syncthreads();   // indices visible

        for (int idx = tid; idx < 128 * 64; idx += 256) {
            const int el = idx >> 6, c = idx & 63;
            const int node = (c < 32) ? ssrc[el] : sdst[el];
            const float4 v = ((const float4*)hmat)[(size_t)node * 32 + (c & 31)];
            __half* p = fA + el * 296 + 4 * c;
            *(half2*)(p)     = __floats2half2_rn(v.x, v.y);
            *(half2*)(p + 2) = __floats2half2_rn(v.z, v.w);
        }
        for (int idx = tid; idx < 128 * 4; idx += 256) {
            const int el = idx >> 2, j = idx & 3;
            const float4 v = ((const float4*)amat)[(size_t)(e0 + el) * 4 + j];
            __half* p = fA + el * 296 + 260 + 4 * j;
            *(half2*)(p)     = __floats2half2_rn(v.x, v.y);
            *(half2*)(p + 2) = __floats2half2_rn(v.z, v.w);
        }
        __syncthreads();   // f ready

        zero_acc(acc);
        gemm_frag(fU, 296, w1U, 18, acc);     // layer 1, K=288
        epi_act(acc, sb1, act);
        __syncthreads();                      // act ready

        zero_acc(acc);
        gemm_frag(actU, 136, w2U, 8, acc);    // layer 2, K=128
        __syncthreads();                      // act reads done
        epi_act(acc, sb2, act);
        __syncthreads();                      // act(silu l2) ready

        if (MODE == 0) {
            // att = sigmoid(mh . Wa + ba)
            if (tid < 128) {
                const half2* ar2 = (const half2*)(act + tid * 136);
                float dot = 0.f;
#pragma unroll 8
                for (int c2 = 0; c2 < 64; ++c2) {
                    float2 m = __half22float2(ar2[c2]);
                    dot = fmaf(m.x, shw[2 * c2], dot);
                    dot = fmaf(m.y, shw[2 * c2 + 1], dot);
                }
                satt[tid] = 1.f / (1.f + __expf(-(dot + hb0)));
            }
            __syncthreads();
            // scatter msg_h = att * mh
            {
                const int row = tid >> 1;
                const int cb  = (tid & 1) * 64;
                const float att = satt[row];
                float* hp = g_hagg + (size_t)sdst[row] * 128 + cb;
                const half2* ar2 = (const half2*)(act + row * 136 + cb);
#pragma unroll
                for (int j = 0; j < 16; ++j) {
                    float2 x0 = __half22float2(ar2[2 * j]);
                    float2 x1 = __half22float2(ar2[2 * j + 1]);
                    red_add_v4(hp + 4 * j, att * x0.x, att * x0.y, att * x1.x, att * x1.y);
                }
            }
        } else {
            if (tid < 128) {
                const half2* ar2 = (const half2*)(act + tid * 136);
                float dot = 0.f;
#pragma unroll 8
                for (int c2 = 0; c2 < 64; ++c2) {
                    float2 m = __half22float2(ar2[c2]);
                    dot = fmaf(m.x, shw[2 * c2], dot);
                    dot = fmaf(m.y, shw[2 * c2 + 1], dot);
                }
                const float dx = sdiff[4 * tid + 0], dy = sdiff[4 * tid + 1];
                const float dz = sdiff[4 * tid + 2], r  = sdiff[4 * tid + 3];
                const float g = dot / (r + 1.f);
                const int d_ = sdst[tid];
                atomicAdd(&g_xagg[d_ * 3 + 0], g * dx);
                atomicAdd(&g_xagg[d_ * 3 + 1], g * dy);
                atomicAdd(&g_xagg[d_ * 3 + 2], g * dz);
            }
        }
        __syncthreads();   // end of tile: act/f reads done before next overwrite
    }
}

// ---------------------------------------------------------------------------
// Persistent node kernel: weights resident, loops node tiles
// ---------------------------------------------------------------------------
#define NOF_W1   0
#define NOF_W2   69632
#define NOF_A    104448
#define NOF_ACT  172032
#define NOF_BIAS 206848
#define NODE_SMEM 207872

__global__ void __launch_bounds__(256, 1)
node_kernel(const float* __restrict__ hmat, const float* __restrict__ coords,
            const float* __restrict__ bn1, const float* __restrict__ bn2,
            float* __restrict__ out)
{
    extern __shared__ __align__(16) char sm[];
    __half* sW1 = (__half*)(sm + NOF_W1);
    __half* sW2 = (__half*)(sm + NOF_W2);
    __half* A   = (__half*)(sm + NOF_A);     // stride 264
    __half* act = (__half*)(sm + NOF_ACT);
    float* sb1  = (float*)(sm + NOF_BIAS);
    float* sb2  = sb1 + 128;

    const uint32_t aU = smem_u32(A), w1U = smem_u32(sW1);
    const uint32_t w2U = smem_u32(sW2), actU = smem_u32(act);
    const int tid = threadIdx.x;

    for (int i = tid; i < 4352; i += 256) ((float4*)sW1)[i] = ((const float4*)g_Wn1)[i];
    for (int i = tid; i < 2176; i += 256) ((float4*)sW2)[i] = ((const float4*)g_Wn2)[i];
    if (tid < 128) { sb1[tid] = bn1[tid]; sb2[tid] = bn2[tid]; }
    __syncthreads();

    const int lane = tid & 31;
    const int wid  = tid >> 5;
    const int wm = wid & 3, wn = wid >> 2;
    float acc[2][8][4];

    for (int t = blockIdx.x; t < NODE_TILES; t += GRID_PERS) {
        const int n0 = t * 128;

        for (int idx = tid; idx < 128 * 64; idx += 256) {
            const int r = idx >> 6, c = idx & 63;
            const int n = n0 + r;
            float4 v = make_float4(0.f, 0.f, 0.f, 0.f);
            if (n < N_NODES)
                v = (c < 32) ? ((const float4*)hmat)[(size_t)n * 32 + c]
                             : ((const float4*)g_hagg)[(size_t)n * 32 + (c - 32)];
            __half* p = A + r * 264 + 4 * c;
            *(half2*)(p)     = __floats2half2_rn(v.x, v.y);
            *(half2*)(p + 2) = __floats2half2_rn(v.z, v.w);
        }
        __syncthreads();

        zero_acc(acc);
        gemm_frag(aU, 264, w1U, 16, acc);
        epi_act(acc, sb1, act);
        __syncthreads();

        zero_acc(acc);
        gemm_frag(actU, 136, w2U, 8, acc);

#pragma unroll
        for (int mt = 0; mt < 2; ++mt)
#pragma unroll
            for (int nt = 0; nt < 8; ++nt) {
                const int row = wm * 32 + mt * 16 + (lane >> 2);
                const int col = wn * 64 + nt * 8 + (lane & 3) * 2;
                const float b0 = sb2[col], b1v = sb2[col + 1];
                int n = n0 + row;
                if (n < N_NODES) {
                    float2 hv = *(const float2*)(hmat + (size_t)n * 128 + col);
                    *(float2*)(out + (size_t)n * 128 + col) =
                        make_float2(hv.x + acc[mt][nt][0] + b0, hv.y + acc[mt][nt][1] + b1v);
                }
                n = n0 + row + 8;
                if (n < N_NODES) {
                    float2 hv = *(const float2*)(hmat + (size_t)n * 128 + col);
                    *(float2*)(out + (size_t)n * 128 + col) =
                        make_float2(hv.x + acc[mt][nt][2] + b0, hv.y + acc[mt][nt][3] + b1v);
                }
            }

        if (tid < 128) {
            const int n = n0 + tid;
            if (n < N_NODES) {
                const size_t base = (size_t)N_NODES * 128;
                out[base + n * 3 + 0] = coords[n * 3 + 0] + g_xagg[n * 3 + 0];
                out[base + n * 3 + 1] = coords[n * 3 + 1] + g_xagg[n * 3 + 1];
                out[base + n * 3 + 2] = coords[n * 3 + 2] + g_xagg[n * 3 + 2];
            }
        }
        __syncthreads();   // act/A reads done before next tile
    }
}

// ---------------------------------------------------------------------------
extern "C" void kernel_launch(void* const* d_in, const int* in_sizes, int n_in,
                              void* d_out, int out_size)
{
    const float* h      = (const float*)d_in[0];
    const float* coords = (const float*)d_in[1];
    const float* a      = (const float*)d_in[2];
    const int*   src    = (const int*)d_in[3];
    const int*   dst    = (const int*)d_in[4];
    const float* We1 = (const float*)d_in[5];
    const float* be1 = (const float*)d_in[6];
    const float* We2 = (const float*)d_in[7];
    const float* be2 = (const float*)d_in[8];
    const float* Wa  = (const float*)d_in[9];
    const float* ba  = (const float*)d_in[10];
    const float* Wn1 = (const float*)d_in[11];
    const float* bn1 = (const float*)d_in[12];
    const float* Wn2 = (const float*)d_in[13];
    const float* bn2 = (const float*)d_in[14];
    const float* Wc1 = (const float*)d_in[15];
    const float* bc1 = (const float*)d_in[16];
    const float* Wc2 = (const float*)d_in[17];
    const float* bc2 = (const float*)d_in[18];
    const float* Wc3 = (const float*)d_in[19];
    float* out = (float*)d_out;

    __half *dW1e, *dW1c, *dWe2, *dWc2;
    cudaGetSymbolAddress((void**)&dW1e, g_W1e);
    cudaGetSymbolAddress((void**)&dW1c, g_W1c);
    cudaGetSymbolAddress((void**)&dWe2, g_We2);
    cudaGetSymbolAddress((void**)&dWc2, g_Wc2);

    cudaFuncSetAttribute(edge_chain_kernel<0>, cudaFuncAttributeMaxDynamicSharedMemorySize, EDGE_SMEM);
    cudaFuncSetAttribute(edge_chain_kernel<1>, cudaFuncAttributeMaxDynamicSharedMemorySize, EDGE_SMEM);
    cudaFuncSetAttribute(node_kernel, cudaFuncAttributeMaxDynamicSharedMemorySize, NODE_SMEM);

    zero_kernel<<<512, 256>>>();
    prep_kernel<<<256, 256>>>(We1, Wc1, We2, Wc2, Wn1, Wn2);
    edge_chain_kernel<0><<<GRID_PERS, 256, EDGE_SMEM>>>(
        h, coords, a, src, dst, dW1e, dWe2, be1, be2, Wa, ba);
    edge_chain_kernel<1><<<GRID_PERS, 256, EDGE_SMEM>>>(
        h, coords, a, src, dst, dW1c, dWc2, bc1, bc2, Wc3, ba);
    node_kernel<<<GRID_PERS, 256, NODE_SMEM>>>(h, coords, bn1, bn2, out);
}

// round 5
// speedup vs baseline: 1.7484x; 1.7484x over previous
#include <cuda_runtime.h>
#include <cuda_fp16.h>
#include <cstdint>
#include <math.h>

#define N_NODES 50000
#define E_EDGES 800000
#define H 128
#define MF 276
#define NTILES (E_EDGES / 128)              // 6250
#define NODE_TILES ((N_NODES + 127) / 128)  // 391

// ---------------------------------------------------------------------------
// Scratch (no cudaMalloc allowed)
// ---------------------------------------------------------------------------
__device__ float  g_hagg[N_NODES * H];
__device__ float  g_xagg[N_NODES * 3];
__device__ __half g_h16[N_NODES * H];
__device__ __half g_a16[E_EDGES * 16];
__device__ __half g_W1e[288 * 136];
__device__ __half g_W1c[288 * 136];
__device__ __half g_We2[128 * 136];
__device__ __half g_Wc2[128 * 136];
__device__ __half g_Wn1[256 * 136];
__device__ __half g_Wn2[128 * 136];

__device__ __forceinline__ uint32_t smem_u32(const void* p) {
    uint32_t a;
    asm("{ .reg .u64 t; cvta.to.shared.u64 t, %1; cvt.u32.u64 %0, t; }"
        : "=r"(a) : "l"(p));
    return a;
}
__device__ __forceinline__ float silu_f(float v) { return v / (1.f + __expf(-v)); }
__device__ __forceinline__ void red_add_v4(float* p, float a, float b, float c, float d) {
    asm volatile("red.global.add.v4.f32 [%0], {%1,%2,%3,%4};"
        :: "l"(p), "f"(a), "f"(b), "f"(c), "f"(d) : "memory");
}

// ---------------------------------------------------------------------------
// 512-thread fp16 GEMM: 16 warps in 4(M)x4(N); C tile 128x128.
// Each warp: 32 rows x 32 cols = 2 mtiles x 4 ntiles of m16n8, acc[2][4][4].
// ---------------------------------------------------------------------------
__device__ __forceinline__ void zero_acc(float (&acc)[2][4][4]) {
#pragma unroll
    for (int mt = 0; mt < 2; ++mt)
#pragma unroll
        for (int nt = 0; nt < 4; ++nt)
#pragma unroll
            for (int i = 0; i < 4; ++i) acc[mt][nt][i] = 0.f;
}

__device__ __forceinline__ void gemm512(uint32_t aBase, int aStride,
                                        uint32_t bBase, int ksteps,
                                        float (&acc)[2][4][4])
{
    const int lane = threadIdx.x & 31;
    const int wid  = threadIdx.x >> 5;
    const int wm   = wid & 3;
    const int wn   = wid >> 2;
    const int arow = wm * 32 + (lane & 15);
    const int acoff = (lane & 16) ? 8 : 0;
    const int brow = lane & 15;
    const int bcol = wn * 32 + ((lane & 16) ? 8 : 0);

    for (int ks = 0; ks < ksteps; ++ks) {
        const int k0 = ks * 16;
        uint32_t a[2][4];
#pragma unroll
        for (int mt = 0; mt < 2; ++mt) {
            uint32_t ad = aBase + (uint32_t)(((arow + mt * 16) * aStride + k0 + acoff) * 2);
            asm volatile("ldmatrix.sync.aligned.m8n8.x4.shared.b16 {%0,%1,%2,%3}, [%4];"
                : "=r"(a[mt][0]), "=r"(a[mt][1]), "=r"(a[mt][2]), "=r"(a[mt][3]) : "r"(ad));
        }
        uint32_t b[4][2];
#pragma unroll
        for (int nt2 = 0; nt2 < 2; ++nt2) {
            uint32_t bd = bBase + (uint32_t)(((k0 + brow) * 136 + bcol + nt2 * 16) * 2);
            asm volatile("ldmatrix.sync.aligned.m8n8.x4.trans.shared.b16 {%0,%1,%2,%3}, [%4];"
                : "=r"(b[2 * nt2][0]), "=r"(b[2 * nt2][1]),
                  "=r"(b[2 * nt2 + 1][0]), "=r"(b[2 * nt2 + 1][1]) : "r"(bd));
        }
#pragma unroll
        for (int mt = 0; mt < 2; ++mt)
#pragma unroll
            for (int nt = 0; nt < 4; ++nt)
                asm volatile("mma.sync.aligned.m16n8k16.row.col.f32.f16.f16.f32 "
                    "{%0,%1,%2,%3}, {%4,%5,%6,%7}, {%8,%9}, {%0,%1,%2,%3};"
                    : "+f"(acc[mt][nt][0]), "+f"(acc[mt][nt][1]),
                      "+f"(acc[mt][nt][2]), "+f"(acc[mt][nt][3])
                    : "r"(a[mt][0]), "r"(a[mt][1]), "r"(a[mt][2]), "r"(a[mt][3]),
                      "r"(b[nt][0]), "r"(b[nt][1]));
    }
}

__device__ __forceinline__ void epi_act512(const float (&acc)[2][4][4],
                                           const float* __restrict__ sb, __half* act)
{
    const int lane = threadIdx.x & 31;
    const int wid  = threadIdx.x >> 5;
    const int wm = wid & 3, wn = wid >> 2;
#pragma unroll
    for (int mt = 0; mt < 2; ++mt)
#pragma unroll
        for (int nt = 0; nt < 4; ++nt) {
            const int row = wm * 32 + mt * 16 + (lane >> 2);
            const int col = wn * 32 + nt * 8 + (lane & 3) * 2;
            const float b0 = sb[col], b1 = sb[col + 1];
            *(half2*)(act + row * 136 + col) =
                __floats2half2_rn(silu_f(acc[mt][nt][0] + b0), silu_f(acc[mt][nt][1] + b1));
            *(half2*)(act + (row + 8) * 136 + col) =
                __floats2half2_rn(silu_f(acc[mt][nt][2] + b0), silu_f(acc[mt][nt][3] + b1));
        }
}

// ---------------------------------------------------------------------------
__global__ void prep_kernel(const float* __restrict__ hmat, const float* __restrict__ amat,
                            const float* __restrict__ We1, const float* __restrict__ Wc1,
                            const float* __restrict__ We2, const float* __restrict__ Wc2,
                            const float* __restrict__ Wn1, const float* __restrict__ Wn2)
{
    const int stride = gridDim.x * blockDim.x;
    const int tid0 = blockIdx.x * blockDim.x + threadIdx.x;
    const __half hz = __float2half_rn(0.f);
    for (int i = tid0; i < N_NODES * H / 2; i += stride) {
        float2 v = ((const float2*)hmat)[i];
        ((half2*)g_h16)[i] = __floats2half2_rn(v.x, v.y);
    }
    for (int i = tid0; i < E_EDGES * 8; i += stride) {
        float2 v = ((const float2*)amat)[i];
        ((half2*)g_a16)[i] = __floats2half2_rn(v.x, v.y);
    }
    for (int i = tid0; i < 288 * 136; i += stride) {
        int k = i / 136, n = i % 136;
        bool ok = (k < MF) && (n < 128);
        g_W1e[i] = ok ? __float2half_rn(We1[k * 128 + n]) : hz;
        g_W1c[i] = ok ? __float2half_rn(Wc1[k * 128 + n]) : hz;
    }
    for (int i = tid0; i < 256 * 136; i += stride) {
        int k = i / 136, n = i % 136;
        g_Wn1[i] = (n < 128) ? __float2half_rn(Wn1[k * 128 + n]) : hz;
    }
    for (int i = tid0; i < 128 * 136; i += stride) {
        int k = i / 136, n = i % 136;
        bool ok = (n < 128);
        g_We2[i] = ok ? __float2half_rn(We2[k * 128 + n]) : hz;
        g_Wc2[i] = ok ? __float2half_rn(Wc2[k * 128 + n]) : hz;
        g_Wn2[i] = ok ? __float2half_rn(Wn2[k * 128 + n]) : hz;
    }
}

__global__ void zero_kernel()
{
    const int total = N_NODES * H + N_NODES * 3;
    for (int i = blockIdx.x * blockDim.x + threadIdx.x; i < total;
         i += gridDim.x * blockDim.x) {
        if (i < N_NODES * H) g_hagg[i] = 0.f;
        else                 g_xagg[i - N_NODES * H] = 0.f;
    }
}

// ---------------------------------------------------------------------------
// Fat persistent edge kernel. Even blocks: edge-MLP chain (mode 0),
// odd blocks: coord-MLP chain (mode 1). 74 blocks per chain.
// ---------------------------------------------------------------------------
#define EOF_W1    0
#define EOF_W2    78336
#define EOF_F     113152      // 128 x 296 halves (stride 592 B)
#define EOF_ACT   188928      // 128 x 136 halves
#define EOF_B1    223744
#define EOF_B2    224256
#define EOF_HW    224768
#define EOF_SDIFF 225280      // 2 x 2048 B (mode1); satt aliases first 512 B (mode0)
#define EOF_SIDX  229376      // 2 x 1024 B: [src 128 | dst 128] ints
#define EDGE_SMEM 231424

__global__ void __launch_bounds__(512, 1)
edge_fat_kernel(const float* __restrict__ coords,
                const int* __restrict__ src, const int* __restrict__ dst,
                const __half* __restrict__ gW1e, const __half* __restrict__ gW2e,
                const __half* __restrict__ gW1c, const __half* __restrict__ gW2c,
                const float* __restrict__ be1, const float* __restrict__ be2,
                const float* __restrict__ Wa,  const float* __restrict__ ba,
                const float* __restrict__ bc1, const float* __restrict__ bc2,
                const float* __restrict__ Wc3)
{
    extern __shared__ __align__(16) char sm[];
    __half* sW1 = (__half*)(sm + EOF_W1);
    __half* sW2 = (__half*)(sm + EOF_W2);
    char*   fB  = sm + EOF_F;
    __half* act = (__half*)(sm + EOF_ACT);
    float* sb1  = (float*)(sm + EOF_B1);
    float* sb2  = (float*)(sm + EOF_B2);
    float* shw  = (float*)(sm + EOF_HW);
    float* satt = (float*)(sm + EOF_SDIFF);
    int*   sidx = (int*)(sm + EOF_SIDX);   // [buf*256 + (src:0..127 | dst:128..255)]

    const uint32_t fU = smem_u32(fB), w1U = smem_u32(sW1);
    const uint32_t w2U = smem_u32(sW2), actU = smem_u32(act);
    const int tid = threadIdx.x;
    const int mode = blockIdx.x & 1;
    const int cb   = blockIdx.x >> 1;

    const __half* gW1 = mode ? gW1c : gW1e;
    const __half* gW2 = mode ? gW2c : gW2e;
    const float*  b1  = mode ? bc1 : be1;
    const float*  b2  = mode ? bc2 : be2;
    const float*  hw  = mode ? Wc3 : Wa;
    const float   hb0 = mode ? 0.f : ba[0];

    for (int i = tid; i < 4896; i += 512) ((float4*)sW1)[i] = ((const float4*)gW1)[i];
    for (int i = tid; i < 2176; i += 512) ((float4*)sW2)[i] = ((const float4*)gW2)[i];
    if (tid < 128) {
        sb1[tid] = b1[tid]; sb2[tid] = b2[tid]; shw[tid] = hw[tid];
        uint2 z2 = make_uint2(0, 0);
        *(uint2*)(fB + tid * 592 + 552) = z2;
        *(uint2*)(fB + tid * 592 + 560) = z2;
        *(uint2*)(fB + tid * 592 + 568) = z2;
    }

    // ---------------- prologue: fully gather tile t0 = cb ----------------
    float pdx = 0.f, pdy = 0.f, pdz = 0.f, pr = 0.f;
    if (tid < 128) {
        const int e = cb * 128 + tid;
        const int s_ = src[e], d_ = dst[e];
        sidx[tid] = s_; sidx[128 + tid] = d_;
        pdx = coords[s_ * 3 + 0] - coords[d_ * 3 + 0];
        pdy = coords[s_ * 3 + 1] - coords[d_ * 3 + 1];
        pdz = coords[s_ * 3 + 2] - coords[d_ * 3 + 2];
        pr  = sqrtf(pdx * pdx + pdy * pdy + pdz * pdz);
        if (mode == 1) {
            float* sd = (float*)(sm + EOF_SDIFF);
            sd[4 * tid + 0] = pdx; sd[4 * tid + 1] = pdy;
            sd[4 * tid + 2] = pdz; sd[4 * tid + 3] = pr;
        }
    }
    __syncthreads();
    {
        float4 rw[8];
#pragma unroll
        for (int i = 0; i < 8; ++i) {
            const int idx = tid + i * 512;
            const int el = idx >> 5, c = idx & 31;
            const int node = (c < 16) ? sidx[el] : sidx[128 + el];
            rw[i] = *(const float4*)(g_h16 + (size_t)node * 128 + (c & 15) * 8);
        }
        float4 aReg = make_float4(0.f, 0.f, 0.f, 0.f);
        if (tid < 256)
            aReg = *(const float4*)(g_a16 + (size_t)(cb * 128 + (tid >> 1)) * 16 + (tid & 1) * 8);
#pragma unroll
        for (int i = 0; i < 8; ++i) {
            const int idx = tid + i * 512;
            const int el = idx >> 5, c = idx & 31;
            *(float4*)(fB + el * 592 + c * 16) = rw[i];
        }
        if (tid < 256) {
            char* p = fB + (tid >> 1) * 592 + 520 + (tid & 1) * 16;
            *(uint2*)(p)     = make_uint2(__float_as_uint(aReg.x), __float_as_uint(aReg.y));
            *(uint2*)(p + 8) = make_uint2(__float_as_uint(aReg.z), __float_as_uint(aReg.w));
        }
        if (tid < 128) {
            half2 d0 = __floats2half2_rn(pr, fabsf(pdx));
            half2 d1 = __floats2half2_rn(fabsf(pdy), fabsf(pdz));
            *(uint2*)(fB + tid * 592 + 512) =
                make_uint2(*(uint32_t*)&d0, *(uint32_t*)&d1);
        }
    }
    __syncthreads();

    float acc[2][4][4];
    int buf = 0;

    // ---------------- persistent tile loop ----------------
    for (int t = cb; t < NTILES; t += 74) {
        const int tn = t + 74;
        const int nbuf = buf ^ 1;
        float4 rw[8];
        float4 aReg = make_float4(0.f, 0.f, 0.f, 0.f);
        const bool pf = (tn < NTILES);

        // P: prefetch indices + issue gathers for tn
        if (pf && tid < 128) {
            const int e = tn * 128 + tid;
            const int s_ = src[e], d_ = dst[e];
            sidx[nbuf * 256 + tid] = s_;
            sidx[nbuf * 256 + 128 + tid] = d_;
            pdx = coords[s_ * 3 + 0] - coords[d_ * 3 + 0];
            pdy = coords[s_ * 3 + 1] - coords[d_ * 3 + 1];
            pdz = coords[s_ * 3 + 2] - coords[d_ * 3 + 2];
            pr  = sqrtf(pdx * pdx + pdy * pdy + pdz * pdz);
            if (mode == 1) {
                float* sd = (float*)(sm + EOF_SDIFF + nbuf * 2048);
                sd[4 * tid + 0] = pdx; sd[4 * tid + 1] = pdy;
                sd[4 * tid + 2] = pdz; sd[4 * tid + 3] = pr;
            }
        }
        __syncthreads();   // sidx[nbuf] visible
        if (pf) {
#pragma unroll
            for (int i = 0; i < 8; ++i) {
                const int idx = tid + i * 512;
                const int el = idx >> 5, c = idx & 31;
                const int node = (c < 16) ? sidx[nbuf * 256 + el]
                                          : sidx[nbuf * 256 + 128 + el];
                rw[i] = *(const float4*)(g_h16 + (size_t)node * 128 + (c & 15) * 8);
            }
            if (tid < 256)
                aReg = *(const float4*)(g_a16 + (size_t)(tn * 128 + (tid >> 1)) * 16 + (tid & 1) * 8);
        }

        // G1: layer-1 GEMM on f(t)
        zero_acc(acc);
        gemm512(fU, 296, w1U, 18, acc);
        __syncthreads();   // f reads done

        // E1: act = silu(l1); commit f(t+1)
        epi_act512(acc, sb1, act);
        if (pf) {
#pragma unroll
            for (int i = 0; i < 8; ++i) {
                const int idx = tid + i * 512;
                const int el = idx >> 5, c = idx & 31;
                *(float4*)(fB + el * 592 + c * 16) = rw[i];
            }
            if (tid < 256) {
                char* p = fB + (tid >> 1) * 592 + 520 + (tid & 1) * 16;
                *(uint2*)(p)     = make_uint2(__float_as_uint(aReg.x), __float_as_uint(aReg.y));
                *(uint2*)(p + 8) = make_uint2(__float_as_uint(aReg.z), __float_as_uint(aReg.w));
            }
            if (tid < 128) {
                half2 d0 = __floats2half2_rn(pr, fabsf(pdx));
                half2 d1 = __floats2half2_rn(fabsf(pdy), fabsf(pdz));
                *(uint2*)(fB + tid * 592 + 512) =
                    make_uint2(*(uint32_t*)&d0, *(uint32_t*)&d1);
            }
        }
        __syncthreads();   // act ready

        // G2: layer-2 GEMM
        zero_acc(acc);
        gemm512(actU, 136, w2U, 8, acc);
        __syncthreads();   // act reads done
        epi_act512(acc, sb2, act);
        __syncthreads();   // act(l2) ready

        // H: head + scatter
        if (mode == 0) {
            if (tid < 128) {
                const half2* ar2 = (const half2*)(act + tid * 136);
                float dot = 0.f;
#pragma unroll 8
                for (int c2 = 0; c2 < 64; ++c2) {
                    float2 m = __half22float2(ar2[c2]);
                    dot = fmaf(m.x, shw[2 * c2], dot);
                    dot = fmaf(m.y, shw[2 * c2 + 1], dot);
                }
                satt[tid] = 1.f / (1.f + __expf(-(dot + hb0)));
            }
            __syncthreads();
            {
                const int row = tid >> 2;
                const int q   = tid & 3;
                const float att = satt[row];
                float* hp = g_hagg + (size_t)sidx[buf * 256 + 128 + row] * 128 + q * 32;
                const half2* ar2 = (const half2*)(act + row * 136 + q * 32);
#pragma unroll
                for (int j = 0; j < 8; ++j) {
                    float2 x0 = __half22float2(ar2[2 * j]);
                    float2 x1 = __half22float2(ar2[2 * j + 1]);
                    red_add_v4(hp + 4 * j, att * x0.x, att * x0.y, att * x1.x, att * x1.y);
                }
            }
        } else {
            if (tid < 128) {
                const half2* ar2 = (const half2*)(act + tid * 136);
                float dot = 0.f;
#pragma unroll 8
                for (int c2 = 0; c2 < 64; ++c2) {
                    float2 m = __half22float2(ar2[c2]);
                    dot = fmaf(m.x, shw[2 * c2], dot);
                    dot = fmaf(m.y, shw[2 * c2 + 1], dot);
                }
                const float* sd = (const float*)(sm + EOF_SDIFF + buf * 2048);
                const float dx = sd[4 * tid + 0], dy = sd[4 * tid + 1];
                const float dz = sd[4 * tid + 2], r  = sd[4 * tid + 3];
                const float g = dot / (r + 1.f);
                const int d_ = sidx[buf * 256 + 128 + tid];
                atomicAdd(&g_xagg[d_ * 3 + 0], g * dx);
                atomicAdd(&g_xagg[d_ * 3 + 1], g * dy);
                atomicAdd(&g_xagg[d_ * 3 + 2], g * dz);
            }
        }
        __syncthreads();   // act/sidx/sdiff reads done before next overwrite
        buf = nbuf;
    }
}

// ---------------------------------------------------------------------------
// Persistent node kernel, 512 threads
// ---------------------------------------------------------------------------
#define NOF_W1   0
#define NOF_W2   69632
#define NOF_A    104448     // 128 x 264 halves (stride 528 B)
#define NOF_ACT  172032
#define NOF_B    206848
#define NODE_SMEM 207872

__global__ void __launch_bounds__(512, 1)
node_kernel(const float* __restrict__ hmat, const float* __restrict__ coords,
            const float* __restrict__ bn1, const float* __restrict__ bn2,
            float* __restrict__ out)
{
    extern __shared__ __align__(16) char sm[];
    __half* sW1 = (__half*)(sm + NOF_W1);
    __half* sW2 = (__half*)(sm + NOF_W2);
    char*   aB  = sm + NOF_A;
    __half* act = (__half*)(sm + NOF_ACT);
    float* sb1  = (float*)(sm + NOF_B);
    float* sb2  = sb1 + 128;

    const uint32_t aU = smem_u32(aB), w1U = smem_u32(sW1);
    const uint32_t w2U = smem_u32(sW2), actU = smem_u32(act);
    const int tid = threadIdx.x;

    for (int i = tid; i < 4352; i += 512) ((float4*)sW1)[i] = ((const float4*)g_Wn1)[i];
    for (int i = tid; i < 2176; i += 512) ((float4*)sW2)[i] = ((const float4*)g_Wn2)[i];
    if (tid < 128) { sb1[tid] = bn1[tid]; sb2[tid] = bn2[tid]; }
    __syncthreads();

    const int lane = tid & 31;
    const int wid  = tid >> 5;
    const int wm = wid & 3, wn = wid >> 2;
    float acc[2][4][4];

    for (int t = blockIdx.x; t < NODE_TILES; t += 148) {
        const int n0 = t * 128;

#pragma unroll
        for (int i = 0; i < 4; ++i) {
            const int idx = tid + i * 512;
            const int el = idx >> 4, c = idx & 15;
            const int n = n0 + el;
            float4 v = make_float4(0.f, 0.f, 0.f, 0.f);
            if (n < N_NODES) v = *(const float4*)(g_h16 + (size_t)n * 128 + c * 8);
            *(float4*)(aB + el * 528 + c * 16) = v;
        }
#pragma unroll
        for (int i = 0; i < 8; ++i) {
            const int idx = tid + i * 512;
            const int el = idx >> 5, c = idx & 31;
            const int n = n0 + el;
            float4 v = make_float4(0.f, 0.f, 0.f, 0.f);
            if (n < N_NODES) v = ((const float4*)g_hagg)[(size_t)n * 32 + c];
            half2 h0 = __floats2half2_rn(v.x, v.y);
            half2 h1 = __floats2half2_rn(v.z, v.w);
            *(uint2*)(aB + el * 528 + 256 + c * 8) =
                make_uint2(*(uint32_t*)&h0, *(uint32_t*)&h1);
        }
        __syncthreads();

        zero_acc(acc);
        gemm512(aU, 264, w1U, 16, acc);
        __syncthreads();
        epi_act512(acc, sb1, act);
        __syncthreads();

        zero_acc(acc);
        gemm512(actU, 136, w2U, 8, acc);

#pragma unroll
        for (int mt = 0; mt < 2; ++mt)
#pragma unroll
            for (int nt = 0; nt < 4; ++nt) {
                const int row = wm * 32 + mt * 16 + (lane >> 2);
                const int col = wn * 32 + nt * 8 + (lane & 3) * 2;
                const float b0 = sb2[col], b1v = sb2[col + 1];
                int n = n0 + row;
                if (n < N_NODES) {
                    float2 hv = *(const float2*)(hmat + (size_t)n * 128 + col);
                    *(float2*)(out + (size_t)n * 128 + col) =
                        make_float2(hv.x + acc[mt][nt][0] + b0, hv.y + acc[mt][nt][1] + b1v);
                }
                n = n0 + row + 8;
                if (n < N_NODES) {
                    float2 hv = *(const float2*)(hmat + (size_t)n * 128 + col);
                    *(float2*)(out + (size_t)n * 128 + col) =
                        make_float2(hv.x + acc[mt][nt][2] + b0, hv.y + acc[mt][nt][3] + b1v);
                }
            }

        if (tid < 128) {
            const int n = n0 + tid;
            if (n < N_NODES) {
                const size_t base = (size_t)N_NODES * 128;
                out[base + n * 3 + 0] = coords[n * 3 + 0] + g_xagg[n * 3 + 0];
                out[base + n * 3 + 1] = coords[n * 3 + 1] + g_xagg[n * 3 + 1];
                out[base + n * 3 + 2] = coords[n * 3 + 2] + g_xagg[n * 3 + 2];
            }
        }
        __syncthreads();
    }
}

// ---------------------------------------------------------------------------
extern "C" void kernel_launch(void* const* d_in, const int* in_sizes, int n_in,
                              void* d_out, int out_size)
{
    const float* h      = (const float*)d_in[0];
    const float* coords = (const float*)d_in[1];
    const float* a      = (const float*)d_in[2];
    const int*   src    = (const int*)d_in[3];
    const int*   dst    = (const int*)d_in[4];
    const float* We1 = (const float*)d_in[5];
    const float* be1 = (const float*)d_in[6];
    const float* We2 = (const float*)d_in[7];
    const float* be2 = (const float*)d_in[8];
    const float* Wa  = (const float*)d_in[9];
    const float* ba  = (const float*)d_in[10];
    const float* Wn1 = (const float*)d_in[11];
    const float* bn1 = (const float*)d_in[12];
    const float* Wn2 = (const float*)d_in[13];
    const float* bn2 = (const float*)d_in[14];
    const float* Wc1 = (const float*)d_in[15];
    const float* bc1 = (const float*)d_in[16];
    const float* Wc2 = (const float*)d_in[17];
    const float* bc2 = (const float*)d_in[18];
    const float* Wc3 = (const float*)d_in[19];
    float* out = (float*)d_out;

    __half *dW1e, *dW1c, *dWe2, *dWc2;
    cudaGetSymbolAddress((void**)&dW1e, g_W1e);
    cudaGetSymbolAddress((void**)&dW1c, g_W1c);
    cudaGetSymbolAddress((void**)&dWe2, g_We2);
    cudaGetSymbolAddress((void**)&dWc2, g_Wc2);

    cudaFuncSetAttribute(edge_fat_kernel, cudaFuncAttributeMaxDynamicSharedMemorySize, EDGE_SMEM);
    cudaFuncSetAttribute(node_kernel, cudaFuncAttributeMaxDynamicSharedMemorySize, NODE_SMEM);

    zero_kernel<<<512, 256>>>();
    prep_kernel<<<1024, 256>>>(h, a, We1, Wc1, We2, Wc2, Wn1, Wn2);
    edge_fat_kernel<<<148, 512, EDGE_SMEM>>>(
        coords, src, dst, dW1e, dWe2, dW1c, dWc2,
        be1, be2, Wa, ba, bc1, bc2, Wc3);
    node_kernel<<<148, 512, NODE_SMEM>>>(h, coords, bn1, bn2, out);
}

// round 7
// speedup vs baseline: 2.3366x; 1.3364x over previous
#include <cuda_runtime.h>
#include <cuda_fp16.h>
#include <cstdint>
#include <math.h>

#define N_NODES 50000
#define E_EDGES 800000
#define H 128
#define MF 276
#define NTILES64 (E_EDGES / 64)             // 12500 64-edge tiles
#define NSTREAMS 148                        // 74 CTAs/mode x 2 groups
#define NODE_TILES ((N_NODES + 127) / 128)  // 391

// ---------------------------------------------------------------------------
__device__ float  g_hagg[N_NODES * H];
__device__ float  g_xagg[N_NODES * 3];
__device__ __half g_h16[N_NODES * H];
__device__ __half g_a16[E_EDGES * 16];
__device__ __half g_W1e[288 * 136];
__device__ __half g_W1c[288 * 136];
__device__ __half g_We2[128 * 136];
__device__ __half g_Wc2[128 * 136];
__device__ __half g_Wn1[256 * 136];
__device__ __half g_Wn2[128 * 136];

__device__ __forceinline__ uint32_t smem_u32(const void* p) {
    uint32_t a;
    asm("{ .reg .u64 t; cvta.to.shared.u64 t, %1; cvt.u32.u64 %0, t; }"
        : "=r"(a) : "l"(p));
    return a;
}
__device__ __forceinline__ float silu_f(float v) {
    return __fdividef(v, 1.f + __expf(-v));
}
__device__ __forceinline__ void red_add_v4(float* p, float a, float b, float c, float d) {
    asm volatile("red.global.add.v4.f32 [%0], {%1,%2,%3,%4};"
        :: "l"(p), "f"(a), "f"(b), "f"(c), "f"(d) : "memory");
}
#define GBAR(id) asm volatile("bar.sync %0, 256;" :: "r"(id) : "memory")

// ---------------------------------------------------------------------------
// Group GEMM: 8 warps (one group) in 2(M)x4(N); C tile 64x128.
// Each warp 32 rows x 32 cols = 2 mtiles x 4 ntiles m16n8, acc[2][4][4].
// ---------------------------------------------------------------------------
__device__ __forceinline__ void zero_acc(float (&acc)[2][4][4]) {
#pragma unroll
    for (int mt = 0; mt < 2; ++mt)
#pragma unroll
        for (int nt = 0; nt < 4; ++nt)
#pragma unroll
            for (int i = 0; i < 4; ++i) acc[mt][nt][i] = 0.f;
}

__device__ __forceinline__ void gemm_g(uint32_t aBase, int aStride,
                                       uint32_t bBase, int ksteps,
                                       float (&acc)[2][4][4])
{
    const int lane = threadIdx.x & 31;
    const int wid  = (threadIdx.x >> 5) & 7;   // warp within group
    const int wm   = wid & 1;
    const int wn   = wid >> 1;
    const int arow = wm * 32 + (lane & 15);
    const int acoff = (lane & 16) ? 8 : 0;
    const int brow = lane & 15;
    const int bcol = wn * 32 + ((lane & 16) ? 8 : 0);

    for (int ks = 0; ks < ksteps; ++ks) {
        const int k0 = ks * 16;
        uint32_t a[2][4];
#pragma unroll
        for (int mt = 0; mt < 2; ++mt) {
            uint32_t ad = aBase + (uint32_t)(((arow + mt * 16) * aStride + k0 + acoff) * 2);
            asm volatile("ldmatrix.sync.aligned.m8n8.x4.shared.b16 {%0,%1,%2,%3}, [%4];"
                : "=r"(a[mt][0]), "=r"(a[mt][1]), "=r"(a[mt][2]), "=r"(a[mt][3]) : "r"(ad));
        }
        uint32_t b[4][2];
#pragma unroll
        for (int nt2 = 0; nt2 < 2; ++nt2) {
            uint32_t bd = bBase + (uint32_t)(((k0 + brow) * 136 + bcol + nt2 * 16) * 2);
            asm volatile("ldmatrix.sync.aligned.m8n8.x4.trans.shared.b16 {%0,%1,%2,%3}, [%4];"
                : "=r"(b[2 * nt2][0]), "=r"(b[2 * nt2][1]),
                  "=r"(b[2 * nt2 + 1][0]), "=r"(b[2 * nt2 + 1][1]) : "r"(bd));
        }
#pragma unroll
        for (int mt = 0; mt < 2; ++mt)
#pragma unroll
            for (int nt = 0; nt < 4; ++nt)
                asm volatile("mma.sync.aligned.m16n8k16.row.col.f32.f16.f16.f32 "
                    "{%0,%1,%2,%3}, {%4,%5,%6,%7}, {%8,%9}, {%0,%1,%2,%3};"
                    : "+f"(acc[mt][nt][0]), "+f"(acc[mt][nt][1]),
                      "+f"(acc[mt][nt][2]), "+f"(acc[mt][nt][3])
                    : "r"(a[mt][0]), "r"(a[mt][1]), "r"(a[mt][2]), "r"(a[mt][3]),
                      "r"(b[nt][0]), "r"(b[nt][1]));
    }
}

__device__ __forceinline__ void epi_act_g(const float (&acc)[2][4][4],
                                          const float* __restrict__ sb, __half* act)
{
    const int lane = threadIdx.x & 31;
    const int wid  = (threadIdx.x >> 5) & 7;
    const int wm = wid & 1, wn = wid >> 1;
#pragma unroll
    for (int mt = 0; mt < 2; ++mt)
#pragma unroll
        for (int nt = 0; nt < 4; ++nt) {
            const int row = wm * 32 + mt * 16 + (lane >> 2);
            const int col = wn * 32 + nt * 8 + (lane & 3) * 2;
            const float b0 = sb[col], b1 = sb[col + 1];
            *(half2*)(act + row * 136 + col) =
                __floats2half2_rn(silu_f(acc[mt][nt][0] + b0), silu_f(acc[mt][nt][1] + b1));
            *(half2*)(act + (row + 8) * 136 + col) =
                __floats2half2_rn(silu_f(acc[mt][nt][2] + b0), silu_f(acc[mt][nt][3] + b1));
        }
}

// ---------------------------------------------------------------------------
__global__ void prep_kernel(const float* __restrict__ hmat, const float* __restrict__ amat,
                            const float* __restrict__ We1, const float* __restrict__ Wc1,
                            const float* __restrict__ We2, const float* __restrict__ Wc2,
                            const float* __restrict__ Wn1, const float* __restrict__ Wn2)
{
    const int stride = gridDim.x * blockDim.x;
    const int tid0 = blockIdx.x * blockDim.x + threadIdx.x;
    const __half hz = __float2half_rn(0.f);
    for (int i = tid0; i < N_NODES * H / 2; i += stride) {
        float2 v = ((const float2*)hmat)[i];
        ((half2*)g_h16)[i] = __floats2half2_rn(v.x, v.y);
    }
    for (int i = tid0; i < E_EDGES * 8; i += stride) {
        float2 v = ((const float2*)amat)[i];
        ((half2*)g_a16)[i] = __floats2half2_rn(v.x, v.y);
    }
    for (int i = tid0; i < 288 * 136; i += stride) {
        int k = i / 136, n = i % 136;
        bool ok = (k < MF) && (n < 128);
        g_W1e[i] = ok ? __float2half_rn(We1[k * 128 + n]) : hz;
        g_W1c[i] = ok ? __float2half_rn(Wc1[k * 128 + n]) : hz;
    }
    for (int i = tid0; i < 256 * 136; i += stride) {
        int k = i / 136, n = i % 136;
        g_Wn1[i] = (n < 128) ? __float2half_rn(Wn1[k * 128 + n]) : hz;
    }
    for (int i = tid0; i < 128 * 136; i += stride) {
        int k = i / 136, n = i % 136;
        bool ok = (n < 128);
        g_We2[i] = ok ? __float2half_rn(We2[k * 128 + n]) : hz;
        g_Wc2[i] = ok ? __float2half_rn(Wc2[k * 128 + n]) : hz;
        g_Wn2[i] = ok ? __float2half_rn(Wn2[k * 128 + n]) : hz;
    }
}

__global__ void zero_kernel()
{
    const int total = N_NODES * H + N_NODES * 3;
    for (int i = blockIdx.x * blockDim.x + threadIdx.x; i < total;
         i += gridDim.x * blockDim.x) {
        if (i < N_NODES * H) g_hagg[i] = 0.f;
        else                 g_xagg[i - N_NODES * H] = 0.f;
    }
}

// ---------------------------------------------------------------------------
// Fat persistent edge kernel: 148 CTAs x 512 thr; CTA parity picks chain;
// two 256-thread groups per CTA, each streaming its own 64-edge tiles.
// Each mode has 74 CTAs x 2 groups = 148 streams; tile stride = 148.
// ---------------------------------------------------------------------------
#define EOF_W1    0           // 78336
#define EOF_W2    78336       // 34816
#define EOF_F     113152      // 2 groups x 64 x 592 B
#define EOF_ACT   188928      // 2 groups x 64 x 272 B
#define EOF_B1    223744
#define EOF_B2    224256
#define EOF_HW    224768
#define EOF_SD    225280      // 2 groups x 2 bufs x 1024 B
#define EOF_SATT  229376      // 2 groups x 256 B
#define EOF_SIDX  229888      // 2 groups x 2 bufs x 512 B
#define EDGE_SMEM 231936

__global__ void __launch_bounds__(512, 1)
edge_fat_kernel(const float* __restrict__ coords,
                const int* __restrict__ src, const int* __restrict__ dst,
                const __half* __restrict__ gW1e, const __half* __restrict__ gW2e,
                const __half* __restrict__ gW1c, const __half* __restrict__ gW2c,
                const float* __restrict__ be1, const float* __restrict__ be2,
                const float* __restrict__ Wa,  const float* __restrict__ ba,
                const float* __restrict__ bc1, const float* __restrict__ bc2,
                const float* __restrict__ Wc3)
{
    extern __shared__ __align__(16) char sm[];
    __half* sW1 = (__half*)(sm + EOF_W1);
    __half* sW2 = (__half*)(sm + EOF_W2);
    float* sb1  = (float*)(sm + EOF_B1);
    float* sb2  = (float*)(sm + EOF_B2);
    float* shw  = (float*)(sm + EOF_HW);

    const int tid  = threadIdx.x;
    const int g    = tid >> 8;            // group 0/1
    const int gtid = tid & 255;
    const int bar  = g + 1;               // named barrier id
    const int mode = blockIdx.x & 1;
    const int cb   = blockIdx.x >> 1;

    char*   fB   = sm + EOF_F + g * 37888;        // 64 x 592 B
    __half* act  = (__half*)(sm + EOF_ACT + g * 17408);
    float*  satt = (float*)(sm + EOF_SATT + g * 256);
    int*    sidx = (int*)(sm + EOF_SIDX + g * 1024);  // [buf*128 + (src64|dst64)]

    const uint32_t fU = smem_u32(fB), actU = smem_u32(act);
    const uint32_t w1U = smem_u32(sW1), w2U = smem_u32(sW2);

    const __half* gW1 = mode ? gW1c : gW1e;
    const __half* gW2 = mode ? gW2c : gW2e;
    const float*  b1  = mode ? bc1 : be1;
    const float*  b2  = mode ? bc2 : be2;
    const float*  hw  = mode ? Wc3 : Wa;
    const float   hb0 = mode ? 0.f : ba[0];

    for (int i = tid; i < 4896; i += 512) ((float4*)sW1)[i] = ((const float4*)gW1)[i];
    for (int i = tid; i < 2176; i += 512) ((float4*)sW2)[i] = ((const float4*)gW2)[i];
    if (tid < 128) { sb1[tid] = b1[tid]; sb2[tid] = b2[tid]; shw[tid] = hw[tid]; }
    if (gtid < 64) {  // permanent zero pad of f cols 276..287 (each group its rows)
        uint2 z2 = make_uint2(0, 0);
        *(uint2*)(fB + gtid * 592 + 552) = z2;
        *(uint2*)(fB + gtid * 592 + 560) = z2;
        *(uint2*)(fB + gtid * 592 + 568) = z2;
    }
    __syncthreads();

    const int t0 = cb * 2 + g;            // this group's first tile (0..147)
    float pdx = 0.f, pdy = 0.f, pdz = 0.f, pr = 0.f;

    // ---------------- prologue: gather tile t0 ----------------
    if (gtid < 64) {
        const int e = t0 * 64 + gtid;
        const int s_ = src[e], d_ = dst[e];
        sidx[gtid] = s_; sidx[64 + gtid] = d_;
        pdx = coords[s_ * 3 + 0] - coords[d_ * 3 + 0];
        pdy = coords[s_ * 3 + 1] - coords[d_ * 3 + 1];
        pdz = coords[s_ * 3 + 2] - coords[d_ * 3 + 2];
        pr  = sqrtf(pdx * pdx + pdy * pdy + pdz * pdz);
        if (mode == 1) {
            float* sd = (float*)(sm + EOF_SD + g * 2048);
            sd[4 * gtid + 0] = pdx; sd[4 * gtid + 1] = pdy;
            sd[4 * gtid + 2] = pdz; sd[4 * gtid + 3] = pr;
        }
    }
    GBAR(bar);
    {
        float4 rw[8];
#pragma unroll
        for (int i = 0; i < 8; ++i) {
            const int idx = gtid + i * 256;
            const int el = idx >> 5, c = idx & 31;
            const int node = (c < 16) ? sidx[el] : sidx[64 + el];
            rw[i] = *(const float4*)(g_h16 + (size_t)node * 128 + (c & 15) * 8);
        }
        float4 aReg = make_float4(0.f, 0.f, 0.f, 0.f);
        if (gtid < 128)
            aReg = *(const float4*)(g_a16 + (size_t)(t0 * 64 + (gtid >> 1)) * 16 + (gtid & 1) * 8);
#pragma unroll
        for (int i = 0; i < 8; ++i) {
            const int idx = gtid + i * 256;
            const int el = idx >> 5, c = idx & 31;
            *(float4*)(fB + el * 592 + c * 16) = rw[i];
        }
        if (gtid < 128) {
            char* p = fB + (gtid >> 1) * 592 + 520 + (gtid & 1) * 16;
            *(uint2*)(p)     = make_uint2(__float_as_uint(aReg.x), __float_as_uint(aReg.y));
            *(uint2*)(p + 8) = make_uint2(__float_as_uint(aReg.z), __float_as_uint(aReg.w));
        }
        if (gtid < 64) {
            half2 d0 = __floats2half2_rn(pr, fabsf(pdx));
            half2 d1 = __floats2half2_rn(fabsf(pdy), fabsf(pdz));
            *(uint2*)(fB + gtid * 592 + 512) =
                make_uint2(*(uint32_t*)&d0, *(uint32_t*)&d1);
        }
    }
    GBAR(bar);

    float acc[2][4][4];
    int buf = 0;

    // ---------------- persistent tile loop ----------------
    for (int t = t0; t < NTILES64; t += NSTREAMS) {
        const int tn = t + NSTREAMS;
        const int nbuf = buf ^ 1;
        float4 rw[8];
        float4 aReg = make_float4(0.f, 0.f, 0.f, 0.f);
        const bool pf = (tn < NTILES64);

        if (pf && gtid < 64) {
            const int e = tn * 64 + gtid;
            const int s_ = src[e], d_ = dst[e];
            sidx[nbuf * 128 + gtid] = s_;
            sidx[nbuf * 128 + 64 + gtid] = d_;
            pdx = coords[s_ * 3 + 0] - coords[d_ * 3 + 0];
            pdy = coords[s_ * 3 + 1] - coords[d_ * 3 + 1];
            pdz = coords[s_ * 3 + 2] - coords[d_ * 3 + 2];
            pr  = sqrtf(pdx * pdx + pdy * pdy + pdz * pdz);
            if (mode == 1) {
                float* sd = (float*)(sm + EOF_SD + g * 2048 + nbuf * 1024);
                sd[4 * gtid + 0] = pdx; sd[4 * gtid + 1] = pdy;
                sd[4 * gtid + 2] = pdz; sd[4 * gtid + 3] = pr;
            }
        }
        GBAR(bar);   // sidx[nbuf] visible
        if (pf) {
#pragma unroll
            for (int i = 0; i < 8; ++i) {
                const int idx = gtid + i * 256;
                const int el = idx >> 5, c = idx & 31;
                const int node = (c < 16) ? sidx[nbuf * 128 + el]
                                          : sidx[nbuf * 128 + 64 + el];
                rw[i] = *(const float4*)(g_h16 + (size_t)node * 128 + (c & 15) * 8);
            }
            if (gtid < 128)
                aReg = *(const float4*)(g_a16 + (size_t)(tn * 64 + (gtid >> 1)) * 16 + (gtid & 1) * 8);
        }

        // G1: layer-1 GEMM, K=288
        zero_acc(acc);
        gemm_g(fU, 296, w1U, 18, acc);
        GBAR(bar);   // f reads done

        // E1: act = silu(l1); commit f(t+NSTREAMS)
        epi_act_g(acc, sb1, act);
        if (pf) {
#pragma unroll
            for (int i = 0; i < 8; ++i) {
                const int idx = gtid + i * 256;
                const int el = idx >> 5, c = idx & 31;
                *(float4*)(fB + el * 592 + c * 16) = rw[i];
            }
            if (gtid < 128) {
                char* p = fB + (gtid >> 1) * 592 + 520 + (gtid & 1) * 16;
                *(uint2*)(p)     = make_uint2(__float_as_uint(aReg.x), __float_as_uint(aReg.y));
                *(uint2*)(p + 8) = make_uint2(__float_as_uint(aReg.z), __float_as_uint(aReg.w));
            }
            if (gtid < 64) {
                half2 d0 = __floats2half2_rn(pr, fabsf(pdx));
                half2 d1 = __floats2half2_rn(fabsf(pdy), fabsf(pdz));
                *(uint2*)(fB + gtid * 592 + 512) =
                    make_uint2(*(uint32_t*)&d0, *(uint32_t*)&d1);
            }
        }
        GBAR(bar);   // act ready

        // G2: layer-2 GEMM, K=128
        zero_acc(acc);
        gemm_g(actU, 136, w2U, 8, acc);
        GBAR(bar);   // act reads done
        epi_act_g(acc, sb2, act);
        GBAR(bar);   // act(l2) ready

        // Head + scatter
        if (mode == 0) {
            if (gtid < 64) {
                const half2* ar2 = (const half2*)(act + gtid * 136);
                float dot = 0.f;
#pragma unroll 8
                for (int c2 = 0; c2 < 64; ++c2) {
                    float2 m = __half22float2(ar2[c2]);
                    dot = fmaf(m.x, shw[2 * c2], dot);
                    dot = fmaf(m.y, shw[2 * c2 + 1], dot);
                }
                satt[gtid] = __fdividef(1.f, 1.f + __expf(-(dot + hb0)));
            }
            GBAR(bar);
            {
                const int row = gtid >> 2;
                const int q   = gtid & 3;
                const float att = satt[row];
                float* hp = g_hagg + (size_t)sidx[buf * 128 + 64 + row] * 128 + q * 32;
                const half2* ar2 = (const half2*)(act + row * 136 + q * 32);
#pragma unroll
                for (int j = 0; j < 8; ++j) {
                    float2 x0 = __half22float2(ar2[2 * j]);
                    float2 x1 = __half22float2(ar2[2 * j + 1]);
                    red_add_v4(hp + 4 * j, att * x0.x, att * x0.y, att * x1.x, att * x1.y);
                }
            }
        } else {
            if (gtid < 64) {
                const half2* ar2 = (const half2*)(act + gtid * 136);
                float dot = 0.f;
#pragma unroll 8
                for (int c2 = 0; c2 < 64; ++c2) {
                    float2 m = __half22float2(ar2[c2]);
                    dot = fmaf(m.x, shw[2 * c2], dot);
                    dot = fmaf(m.y, shw[2 * c2 + 1], dot);
                }
                const float* sd = (const float*)(sm + EOF_SD + g * 2048 + buf * 1024);
                const float dx = sd[4 * gtid + 0], dy = sd[4 * gtid + 1];
                const float dz = sd[4 * gtid + 2], r  = sd[4 * gtid + 3];
                const float gg = dot / (r + 1.f);
                const int d_ = sidx[buf * 128 + 64 + gtid];
                atomicAdd(&g_xagg[d_ * 3 + 0], gg * dx);
                atomicAdd(&g_xagg[d_ * 3 + 1], gg * dy);
                atomicAdd(&g_xagg[d_ * 3 + 2], gg * dz);
            }
        }
        GBAR(bar);   // act/sidx/sdiff reads done before next overwrite
        buf = nbuf;
    }
}

// ---------------------------------------------------------------------------
// Persistent node kernel, 512 threads, 16 warps 4x4
// ---------------------------------------------------------------------------
__device__ __forceinline__ void gemm512(uint32_t aBase, int aStride,
                                        uint32_t bBase, int ksteps,
                                        float (&acc)[2][4][4])
{
    const int lane = threadIdx.x & 31;
    const int wid  = threadIdx.x >> 5;
    const int wm   = wid & 3;
    const int wn   = wid >> 2;
    const int arow = wm * 32 + (lane & 15);
    const int acoff = (lane & 16) ? 8 : 0;
    const int brow = lane & 15;
    const int bcol = wn * 32 + ((lane & 16) ? 8 : 0);

    for (int ks = 0; ks < ksteps; ++ks) {
        const int k0 = ks * 16;
        uint32_t a[2][4];
#pragma unroll
        for (int mt = 0; mt < 2; ++mt) {
            uint32_t ad = aBase + (uint32_t)(((arow + mt * 16) * aStride + k0 + acoff) * 2);
            asm volatile("ldmatrix.sync.aligned.m8n8.x4.shared.b16 {%0,%1,%2,%3}, [%4];"
                : "=r"(a[mt][0]), "=r"(a[mt][1]), "=r"(a[mt][2]), "=r"(a[mt][3]) : "r"(ad));
        }
        uint32_t b[4][2];
#pragma unroll
        for (int nt2 = 0; nt2 < 2; ++nt2) {
            uint32_t bd = bBase + (uint32_t)(((k0 + brow) * 136 + bcol + nt2 * 16) * 2);
            asm volatile("ldmatrix.sync.aligned.m8n8.x4.trans.shared.b16 {%0,%1,%2,%3}, [%4];"
                : "=r"(b[2 * nt2][0]), "=r"(b[2 * nt2][1]),
                  "=r"(b[2 * nt2 + 1][0]), "=r"(b[2 * nt2 + 1][1]) : "r"(bd));
        }
#pragma unroll
        for (int mt = 0; mt < 2; ++mt)
#pragma unroll
            for (int nt = 0; nt < 4; ++nt)
                asm volatile("mma.sync.aligned.m16n8k16.row.col.f32.f16.f16.f32 "
                    "{%0,%1,%2,%3}, {%4,%5,%6,%7}, {%8,%9}, {%0,%1,%2,%3};"
                    : "+f"(acc[mt][nt][0]), "+f"(acc[mt][nt][1]),
                      "+f"(acc[mt][nt][2]), "+f"(acc[mt][nt][3])
                    : "r"(a[mt][0]), "r"(a[mt][1]), "r"(a[mt][2]), "r"(a[mt][3]),
                      "r"(b[nt][0]), "r"(b[nt][1]));
    }
}

#define NOF_W1   0
#define NOF_W2   69632
#define NOF_A    104448     // 128 x 528 B
#define NOF_ACT  172032
#define NOF_B    206848
#define NODE_SMEM 207872

__global__ void __launch_bounds__(512, 1)
node_kernel(const float* __restrict__ hmat, const float* __restrict__ coords,
            const float* __restrict__ bn1, const float* __restrict__ bn2,
            float* __restrict__ out)
{
    extern __shared__ __align__(16) char sm[];
    __half* sW1 = (__half*)(sm + NOF_W1);
    __half* sW2 = (__half*)(sm + NOF_W2);
    char*   aB  = sm + NOF_A;
    __half* act = (__half*)(sm + NOF_ACT);
    float* sb1  = (float*)(sm + NOF_B);
    float* sb2  = sb1 + 128;

    const uint32_t aU = smem_u32(aB), w1U = smem_u32(sW1);
    const uint32_t w2U = smem_u32(sW2), actU = smem_u32(act);
    const int tid = threadIdx.x;

    for (int i = tid; i < 4352; i += 512) ((float4*)sW1)[i] = ((const float4*)g_Wn1)[i];
    for (int i = tid; i < 2176; i += 512) ((float4*)sW2)[i] = ((const float4*)g_Wn2)[i];
    if (tid < 128) { sb1[tid] = bn1[tid]; sb2[tid] = bn2[tid]; }
    __syncthreads();

    const int lane = tid & 31;
    const int wid  = tid >> 5;
    const int wm = wid & 3, wn = wid >> 2;
    float acc[2][4][4];

    for (int t = blockIdx.x; t < NODE_TILES; t += 148) {
        const int n0 = t * 128;

#pragma unroll
        for (int i = 0; i < 4; ++i) {
            const int idx = tid + i * 512;
            const int el = idx >> 4, c = idx & 15;
            const int n = n0 + el;
            float4 v = make_float4(0.f, 0.f, 0.f, 0.f);
            if (n < N_NODES) v = *(const float4*)(g_h16 + (size_t)n * 128 + c * 8);
            *(float4*)(aB + el * 528 + c * 16) = v;
        }
#pragma unroll
        for (int i = 0; i < 8; ++i) {
            const int idx = tid + i * 512;
            const int el = idx >> 5, c = idx & 31;
            const int n = n0 + el;
            float4 v = make_float4(0.f, 0.f, 0.f, 0.f);
            if (n < N_NODES) v = ((const float4*)g_hagg)[(size_t)n * 32 + c];
            half2 h0 = __floats2half2_rn(v.x, v.y);
            half2 h1 = __floats2half2_rn(v.z, v.w);
            *(uint2*)(aB + el * 528 + 256 + c * 8) =
                make_uint2(*(uint32_t*)&h0, *(uint32_t*)&h1);
        }
        __syncthreads();

        zero_acc(acc);
        gemm512(aU, 264, w1U, 16, acc);
        __syncthreads();
        {
#pragma unroll
            for (int mt = 0; mt < 2; ++mt)
#pragma unroll
                for (int nt = 0; nt < 4; ++nt) {
                    const int row = wm * 32 + mt * 16 + (lane >> 2);
                    const int col = wn * 32 + nt * 8 + (lane & 3) * 2;
                    const float b0 = sb1[col], b1v = sb1[col + 1];
                    *(half2*)(act + row * 136 + col) =
                        __floats2half2_rn(silu_f(acc[mt][nt][0] + b0), silu_f(acc[mt][nt][1] + b1v));
                    *(half2*)(act + (row + 8) * 136 + col) =
                        __floats2half2_rn(silu_f(acc[mt][nt][2] + b0), silu_f(acc[mt][nt][3] + b1v));
                }
        }
        __syncthreads();

        zero_acc(acc);
        gemm512(actU, 136, w2U, 8, acc);

#pragma unroll
        for (int mt = 0; mt < 2; ++mt)
#pragma unroll
            for (int nt = 0; nt < 4; ++nt) {
                const int row = wm * 32 + mt * 16 + (lane >> 2);
                const int col = wn * 32 + nt * 8 + (lane & 3) * 2;
                const float b0 = sb2[col], b1v = sb2[col + 1];
                int n = n0 + row;
                if (n < N_NODES) {
                    float2 hv = *(const float2*)(hmat + (size_t)n * 128 + col);
                    *(float2*)(out + (size_t)n * 128 + col) =
                        make_float2(hv.x + acc[mt][nt][0] + b0, hv.y + acc[mt][nt][1] + b1v);
                }
                n = n0 + row + 8;
                if (n < N_NODES) {
                    float2 hv = *(const float2*)(hmat + (size_t)n * 128 + col);
                    *(float2*)(out + (size_t)n * 128 + col) =
                        make_float2(hv.x + acc[mt][nt][2] + b0, hv.y + acc[mt][nt][3] + b1v);
                }
            }

        if (tid < 128) {
            const int n = n0 + tid;
            if (n < N_NODES) {
                const size_t base = (size_t)N_NODES * 128;
                out[base + n * 3 + 0] = coords[n * 3 + 0] + g_xagg[n * 3 + 0];
                out[base + n * 3 + 1] = coords[n * 3 + 1] + g_xagg[n * 3 + 1];
                out[base + n * 3 + 2] = coords[n * 3 + 2] + g_xagg[n * 3 + 2];
            }
        }
        __syncthreads();
    }
}

// ---------------------------------------------------------------------------
extern "C" void kernel_launch(void* const* d_in, const int* in_sizes, int n_in,
                              void* d_out, int out_size)
{
    const float* h      = (const float*)d_in[0];
    const float* coords = (const float*)d_in[1];
    const float* a      = (const float*)d_in[2];
    const int*   src    = (const int*)d_in[3];
    const int*   dst    = (const int*)d_in[4];
    const float* We1 = (const float*)d_in[5];
    const float* be1 = (const float*)d_in[6];
    const float* We2 = (const float*)d_in[7];
    const float* be2 = (const float*)d_in[8];
    const float* Wa  = (const float*)d_in[9];
    const float* ba  = (const float*)d_in[10];
    const float* Wn1 = (const float*)d_in[11];
    const float* bn1 = (const float*)d_in[12];
    const float* Wn2 = (const float*)d_in[13];
    const float* bn2 = (const float*)d_in[14];
    const float* Wc1 = (const float*)d_in[15];
    const float* bc1 = (const float*)d_in[16];
    const float* Wc2 = (const float*)d_in[17];
    const float* bc2 = (const float*)d_in[18];
    const float* Wc3 = (const float*)d_in[19];
    float* out = (float*)d_out;

    __half *dW1e, *dW1c, *dWe2, *dWc2;
    cudaGetSymbolAddress((void**)&dW1e, g_W1e);
    cudaGetSymbolAddress((void**)&dW1c, g_W1c);
    cudaGetSymbolAddress((void**)&dWe2, g_We2);
    cudaGetSymbolAddress((void**)&dWc2, g_Wc2);

    cudaFuncSetAttribute(edge_fat_kernel, cudaFuncAttributeMaxDynamicSharedMemorySize, EDGE_SMEM);
    cudaFuncSetAttribute(node_kernel, cudaFuncAttributeMaxDynamicSharedMemorySize, NODE_SMEM);

    zero_kernel<<<512, 256>>>();
    prep_kernel<<<1024, 256>>>(h, a, We1, Wc1, We2, Wc2, Wn1, Wn2);
    edge_fat_kernel<<<148, 512, EDGE_SMEM>>>(
        coords, src, dst, dW1e, dWe2, dW1c, dWc2,
        be1, be2, Wa, ba, bc1, bc2, Wc3);
    node_kernel<<<148, 512, NODE_SMEM>>>(h, coords, bn1, bn2, out);
}